// round 16
// baseline (speedup 1.0000x reference)
#include <cuda_runtime.h>
#include <cstdint>

constexpr int K  = 4096;
constexpr int N  = 11008;
constexpr int NW = N / 8;        // qzeros columns = 1376
constexpr int WR = K / 8;        // packed weight rows = 512
constexpr int N4 = N / 4;        // float4 columns = 2752

// nib + 2^23, exact in fp32. (w+M) - (z+M) == w - z exactly for 0..15.
#define MAGIC 0x4B000000u

__device__ __forceinline__ float nib2f(unsigned word, int sh) {
    return __uint_as_float(((word >> sh) & 15u) | MAGIC);
}

__global__ __launch_bounds__(256) void dequant_kernel(
    const int*   __restrict__ qweight,  // [K/8, N]
    const int*   __restrict__ qzeros,   // [G, N/8]
    const float* __restrict__ scales,   // [G, N]
    const int*   __restrict__ g_idx,    // [K]
    float*       __restrict__ out)      // [K, N]
{
    const int n4 = blockIdx.x * blockDim.x + threadIdx.x;  // over N/4
    const int wr = blockIdx.y;                             // packed row 0..511
    if (n4 >= N4) return;
    const int n = n4 * 4;

    // 4 packed weight words: 4 consecutive output columns, 8 k-rows each
    const uint4 qw = *reinterpret_cast<const uint4*>(qweight + (size_t)wr * N + n);

    // group ids for the 8 k-rows (warp-uniform broadcast loads)
    const int4 gi0 = *reinterpret_cast<const int4*>(g_idx + wr * 8);
    const int4 gi1 = *reinterpret_cast<const int4*>(g_idx + wr * 8 + 4);
    const int gs[8] = {gi0.x, gi0.y, gi0.z, gi0.w, gi1.x, gi1.y, gi1.z, gi1.w};

    const int zsh = 4 * (n & 7);   // 0 or 16
    const int nz  = n >> 3;        // qzeros column

    float* orow = out + (size_t)wr * 8 * N + n;

    // group-hoisted state: g_idx is sorted, so the group is constant within
    // this 8-row span except at <=31 of 512 word-rows. The check is
    // warp-uniform (same g across the warp) -> cheap uniform branch.
    int gcur = -1;
    float4 sc;
    float fz0 = 0.f, fz1 = 0.f, fz2 = 0.f, fz3 = 0.f;

#pragma unroll
    for (int j = 0; j < 8; j++) {
        const int g = gs[j];
        if (g != gcur) {
            gcur = g;
            const unsigned zw = (unsigned)__ldg(qzeros + g * NW + nz);
            fz0 = nib2f(zw, zsh + 0);
            fz1 = nib2f(zw, zsh + 4);
            fz2 = nib2f(zw, zsh + 8);
            fz3 = nib2f(zw, zsh + 12);
            sc  = *reinterpret_cast<const float4*>(scales + (size_t)g * N + n);
        }

        const int sh = 4 * j;
        float4 o;
        o.x = sc.x * (nib2f(qw.x, sh) - fz0);
        o.y = sc.y * (nib2f(qw.y, sh) - fz1);
        o.z = sc.z * (nib2f(qw.z, sh) - fz2);
        o.w = sc.w * (nib2f(qw.w, sh) - fz3);

        // streaming store: output is never re-read, keep scales in L2
        __stcs(reinterpret_cast<float4*>(orow + (size_t)j * N), o);
    }
}

extern "C" void kernel_launch(void* const* d_in, const int* in_sizes, int n_in,
                              void* d_out, int out_size)
{
    const int*   qweight = (const int*)  d_in[0];
    const int*   qzeros  = (const int*)  d_in[1];
    const float* scales  = (const float*)d_in[2];
    const int*   g_idx   = (const int*)  d_in[3];
    float*       out     = (float*)      d_out;

    dim3 block(256);
    dim3 grid((N4 + 255) / 256, WR);
    dequant_kernel<<<grid, block>>>(qweight, qzeros, scales, g_idx, out);
}